// round 3
// baseline (speedup 1.0000x reference)
#include <cuda_runtime.h>

#define NNODES 50000
#define DIM    128
#define NHOPS  3
#define SIGMA_F 0.1f

// ---------------------------------------------------------------------------
// Scratch (allocation-free rule: __device__ globals)
// ---------------------------------------------------------------------------
__device__ float g_aggr[NNODES * DIM];   // 25.6 MB accumulator
__device__ int   g_is64;                 // edge_index dtype flag

// ---------------------------------------------------------------------------
// Threefry-2x32 (20 rounds) — must match JAX bit-for-bit
// ---------------------------------------------------------------------------
__host__ __device__ __forceinline__ void tf_round(unsigned& x0, unsigned& x1, int r) {
    x0 += x1;
#ifdef __CUDA_ARCH__
    x1 = __funnelshift_l(x1, x1, r);
#else
    x1 = (x1 << r) | (x1 >> (32 - r));
#endif
    x1 ^= x0;
}

__host__ __device__ __forceinline__ void threefry2x32(
    unsigned k0, unsigned k1, unsigned x0, unsigned x1,
    unsigned& o0, unsigned& o1)
{
    unsigned k2 = k0 ^ k1 ^ 0x1BD11BDAu;
    x0 += k0; x1 += k1;
    tf_round(x0,x1,13); tf_round(x0,x1,15); tf_round(x0,x1,26); tf_round(x0,x1, 6);
    x0 += k1; x1 += k2 + 1u;
    tf_round(x0,x1,17); tf_round(x0,x1,29); tf_round(x0,x1,16); tf_round(x0,x1,24);
    x0 += k2; x1 += k0 + 2u;
    tf_round(x0,x1,13); tf_round(x0,x1,15); tf_round(x0,x1,26); tf_round(x0,x1, 6);
    x0 += k0; x1 += k1 + 3u;
    tf_round(x0,x1,17); tf_round(x0,x1,29); tf_round(x0,x1,16); tf_round(x0,x1,24);
    x0 += k1; x1 += k2 + 4u;
    tf_round(x0,x1,13); tf_round(x0,x1,15); tf_round(x0,x1,26); tf_round(x0,x1, 6);
    x0 += k2; x1 += k0 + 5u;
    o0 = x0; o1 = x1;
}

// XLA ErfInv32 polynomial (Giles)
__device__ __forceinline__ float erfinv_f(float x) {
    float w = -log1pf(-x * x);
    float p;
    if (w < 5.0f) {
        w -= 2.5f;
        p =              2.81022636e-08f;
        p = fmaf(p, w,   3.43273939e-07f);
        p = fmaf(p, w,  -3.5233877e-06f);
        p = fmaf(p, w,  -4.39150654e-06f);
        p = fmaf(p, w,   0.00021858087f);
        p = fmaf(p, w,  -0.00125372503f);
        p = fmaf(p, w,  -0.00417768164f);
        p = fmaf(p, w,   0.246640727f);
        p = fmaf(p, w,   1.50140941f);
    } else {
        w = sqrtf(w) - 3.0f;
        p =             -0.000200214257f;
        p = fmaf(p, w,   0.000100950558f);
        p = fmaf(p, w,   0.00134934322f);
        p = fmaf(p, w,  -0.00367342844f);
        p = fmaf(p, w,   0.00573950773f);
        p = fmaf(p, w,  -0.0076224613f);
        p = fmaf(p, w,   0.00943887047f);
        p = fmaf(p, w,   1.00167406f);
        p = fmaf(p, w,   2.83297682f);
    }
    return p * x;
}

// jax.random.normal element (threefry_partitionable path):
// bits = o0 ^ o1 of threefry(key, (0, idx)); uniform in [nextafter(-1,0), 1); sqrt(2)*erfinv
__device__ __forceinline__ float jax_normal(unsigned k0, unsigned k1, unsigned idx) {
    unsigned o0, o1;
    threefry2x32(k0, k1, 0u, idx, o0, o1);
    unsigned bits = o0 ^ o1;
    float u01 = __uint_as_float((bits >> 9) | 0x3F800000u) - 1.0f;
    const float LO = -0.99999994f;          // nextafterf(-1, 0)
    float u = fmaxf(LO, u01 * 2.0f + LO);   // (1.0f - LO) rounds to exactly 2.0f
    return 1.41421356f * erfinv_f(u);       // sqrt(2) in f32
}

// ---------------------------------------------------------------------------
// dtype detection: int64 edge_index (values < 50000) has odd 32-bit words == 0
// ---------------------------------------------------------------------------
__global__ void detect_kernel(const unsigned* __restrict__ w) {
    int z = (w[1] == 0u) + (w[3] == 0u) + (w[5] == 0u) + (w[7] == 0u) + (w[9] == 0u);
    g_is64 = (z == 5) ? 1 : 0;
}

// ---------------------------------------------------------------------------
// init: h0 = normalize(x) -> out[0]; zero aggr. One warp per row.
// ---------------------------------------------------------------------------
__global__ __launch_bounds__(256) void init_kernel(
    const float* __restrict__ x, float* __restrict__ out0)
{
    int row  = (blockIdx.x * blockDim.x + threadIdx.x) >> 5;
    int lane = threadIdx.x & 31;
    if (row >= NNODES) return;
    float4 v = __ldg((const float4*)(x + (size_t)row * DIM) + lane);
    float ss = v.x*v.x + v.y*v.y + v.z*v.z + v.w*v.w;
#pragma unroll
    for (int o = 16; o; o >>= 1) ss += __shfl_xor_sync(0xffffffffu, ss, o);
    float inv = 1.0f / fmaxf(sqrtf(ss), 1e-12f);
    v.x *= inv; v.y *= inv; v.z *= inv; v.w *= inv;
    ((float4*)(out0 + (size_t)row * DIM))[lane] = v;
    ((float4*)(g_aggr + (size_t)row * DIM))[lane] = make_float4(0.f, 0.f, 0.f, 0.f);
}

// ---------------------------------------------------------------------------
// edge: one warp per edge. dot(h[src],h[dst]) -> sigmoid -> red.v4 into aggr[dst]
// h rows are L2-resident (25.6 MB), so this is L2-bandwidth bound.
// ---------------------------------------------------------------------------
__global__ __launch_bounds__(256) void edge_kernel(
    const float* __restrict__ h, const void* __restrict__ ei, int E)
{
    int e = (blockIdx.x * blockDim.x + threadIdx.x) >> 5;
    if (e >= E) return;
    int lane = threadIdx.x & 31;

    int s, d;
    if (g_is64) {
        const long long* p = (const long long*)ei;
        s = (int)__ldg(p + e);
        d = (int)__ldg(p + e + E);
    } else {
        const int* p = (const int*)ei;
        s = __ldg(p + e);
        d = __ldg(p + e + E);
    }

    float4 a = __ldg((const float4*)(h + (size_t)s * DIM) + lane);
    float4 b = __ldg((const float4*)(h + (size_t)d * DIM) + lane);
    float dot = a.x*b.x + a.y*b.y + a.z*b.z + a.w*b.w;
#pragma unroll
    for (int o = 16; o; o >>= 1) dot += __shfl_xor_sync(0xffffffffu, dot, o);

    float alpha = 1.0f / (1.0f + expf(-dot));
    float4 v = make_float4(alpha * a.x, alpha * a.y, alpha * a.z, alpha * a.w);

    float* p = g_aggr + (size_t)d * DIM + lane * 4;
    asm volatile("red.global.add.v4.f32 [%0], {%1,%2,%3,%4};"
                 :: "l"(p), "f"(v.x), "f"(v.y), "f"(v.z), "f"(v.w) : "memory");
}

// ---------------------------------------------------------------------------
// hop: h_{k+1} = normalize(aggr + sigma*noise) -> out[k+1]; re-zero aggr.
// One warp per row, 4 threefry evals per lane.
// ---------------------------------------------------------------------------
__global__ __launch_bounds__(256) void hop_kernel(
    float* __restrict__ out, unsigned k0, unsigned k1)
{
    int row  = (blockIdx.x * blockDim.x + threadIdx.x) >> 5;
    int lane = threadIdx.x & 31;
    if (row >= NNODES) return;

    float4* ap = (float4*)(g_aggr + (size_t)row * DIM) + lane;
    float4 v = *ap;
    unsigned base = (unsigned)row * DIM + (unsigned)lane * 4;
    v.x += SIGMA_F * jax_normal(k0, k1, base + 0);
    v.y += SIGMA_F * jax_normal(k0, k1, base + 1);
    v.z += SIGMA_F * jax_normal(k0, k1, base + 2);
    v.w += SIGMA_F * jax_normal(k0, k1, base + 3);

    float ss = v.x*v.x + v.y*v.y + v.z*v.z + v.w*v.w;
#pragma unroll
    for (int o = 16; o; o >>= 1) ss += __shfl_xor_sync(0xffffffffu, ss, o);
    float inv = 1.0f / fmaxf(sqrtf(ss), 1e-12f);
    v.x *= inv; v.y *= inv; v.z *= inv; v.w *= inv;

    ((float4*)(out + (size_t)row * DIM))[lane] = v;
    *ap = make_float4(0.f, 0.f, 0.f, 0.f);   // ready for next hop
}

// ---------------------------------------------------------------------------
// launch
// ---------------------------------------------------------------------------
extern "C" void kernel_launch(void* const* d_in, const int* in_sizes, int n_in,
                              void* d_out, int out_size)
{
    // robust input mapping by element count
    int i_x = 0, i_e = 1;
    if (in_sizes[0] != NNODES * DIM) { i_x = 1; i_e = 0; }
    const float* x  = (const float*)d_in[i_x];
    const void*  ei = d_in[i_e];
    int E = in_sizes[i_e] / 2;

    float* out = (float*)d_out;

    // fold-like split of jax.random.key(1) into NHOPS subkeys (host-side, exact)
    unsigned keys[NHOPS][2];
    for (unsigned k = 0; k < NHOPS; ++k)
        threefry2x32(0u, 1u, 0u, k, keys[k][0], keys[k][1]);

    detect_kernel<<<1, 1>>>((const unsigned*)ei);

    const int ROW_BLOCKS = (NNODES * 32 + 255) / 256;
    init_kernel<<<ROW_BLOCKS, 256>>>(x, out);

    for (int k = 0; k < NHOPS; ++k) {
        long long ethreads = (long long)E * 32;
        unsigned eblocks = (unsigned)((ethreads + 255) / 256);
        edge_kernel<<<eblocks, 256>>>(out + (size_t)k * NNODES * DIM, ei, E);
        hop_kernel<<<ROW_BLOCKS, 256>>>(out + (size_t)(k + 1) * NNODES * DIM,
                                        keys[k][0], keys[k][1]);
    }
}

// round 5
// speedup vs baseline: 1.8485x; 1.8485x over previous
#include <cuda_runtime.h>

#define NNODES 50000
#define DIM    128
#define NHOPS  3
#define SIGMA_F 0.1f
#define MAXE   800000
#define NCHUNK 196            // ceil(50000/256)

// ---------------------------------------------------------------------------
// Scratch (__device__ globals — allocation-free rule)
// ---------------------------------------------------------------------------
__device__ int g_cnt[NNODES];        // in-degree histogram
__device__ int g_off[NNODES + 1];    // segment offsets (CSR by dst)
__device__ int g_cur[NNODES];        // scatter cursors
__device__ int g_src[MAXE];          // src indices sorted by dst
__device__ int g_part[256];          // block partial sums for scan
__device__ int g_is64;               // edge_index dtype flag

// ---------------------------------------------------------------------------
// Threefry-2x32 (20 rounds) — matches JAX bit-for-bit (verified R2)
// ---------------------------------------------------------------------------
__host__ __device__ __forceinline__ void tf_round(unsigned& x0, unsigned& x1, int r) {
    x0 += x1;
#ifdef __CUDA_ARCH__
    x1 = __funnelshift_l(x1, x1, r);
#else
    x1 = (x1 << r) | (x1 >> (32 - r));
#endif
    x1 ^= x0;
}

__host__ __device__ __forceinline__ void threefry2x32(
    unsigned k0, unsigned k1, unsigned x0, unsigned x1,
    unsigned& o0, unsigned& o1)
{
    unsigned k2 = k0 ^ k1 ^ 0x1BD11BDAu;
    x0 += k0; x1 += k1;
    tf_round(x0,x1,13); tf_round(x0,x1,15); tf_round(x0,x1,26); tf_round(x0,x1, 6);
    x0 += k1; x1 += k2 + 1u;
    tf_round(x0,x1,17); tf_round(x0,x1,29); tf_round(x0,x1,16); tf_round(x0,x1,24);
    x0 += k2; x1 += k0 + 2u;
    tf_round(x0,x1,13); tf_round(x0,x1,15); tf_round(x0,x1,26); tf_round(x0,x1, 6);
    x0 += k0; x1 += k1 + 3u;
    tf_round(x0,x1,17); tf_round(x0,x1,29); tf_round(x0,x1,16); tf_round(x0,x1,24);
    x0 += k1; x1 += k2 + 4u;
    tf_round(x0,x1,13); tf_round(x0,x1,15); tf_round(x0,x1,26); tf_round(x0,x1, 6);
    x0 += k2; x1 += k0 + 5u;
    o0 = x0; o1 = x1;
}

// XLA ErfInv32 polynomial (Giles)
__device__ __forceinline__ float erfinv_f(float x) {
    float w = -log1pf(-x * x);
    float p;
    if (w < 5.0f) {
        w -= 2.5f;
        p =              2.81022636e-08f;
        p = fmaf(p, w,   3.43273939e-07f);
        p = fmaf(p, w,  -3.5233877e-06f);
        p = fmaf(p, w,  -4.39150654e-06f);
        p = fmaf(p, w,   0.00021858087f);
        p = fmaf(p, w,  -0.00125372503f);
        p = fmaf(p, w,  -0.00417768164f);
        p = fmaf(p, w,   0.246640727f);
        p = fmaf(p, w,   1.50140941f);
    } else {
        w = sqrtf(w) - 3.0f;
        p =             -0.000200214257f;
        p = fmaf(p, w,   0.000100950558f);
        p = fmaf(p, w,   0.00134934322f);
        p = fmaf(p, w,  -0.00367342844f);
        p = fmaf(p, w,   0.00573950773f);
        p = fmaf(p, w,  -0.0076224613f);
        p = fmaf(p, w,   0.00943887047f);
        p = fmaf(p, w,   1.00167406f);
        p = fmaf(p, w,   2.83297682f);
    }
    return p * x;
}

__device__ __forceinline__ float jax_normal(unsigned k0, unsigned k1, unsigned idx) {
    unsigned o0, o1;
    threefry2x32(k0, k1, 0u, idx, o0, o1);
    unsigned bits = o0 ^ o1;
    float u01 = __uint_as_float((bits >> 9) | 0x3F800000u) - 1.0f;
    const float LO = -0.99999994f;          // nextafterf(-1, 0)
    float u = fmaxf(LO, u01 * 2.0f + LO);   // (1.0f - LO) rounds to exactly 2.0f
    return 1.41421356f * erfinv_f(u);       // sqrt(2) in f32
}

// ---------------------------------------------------------------------------
// dtype detection: int64 edge_index (values < 50000) has odd 32-bit words == 0
// ---------------------------------------------------------------------------
__global__ void detect_kernel(const unsigned* __restrict__ w) {
    int z = (w[1] == 0u) + (w[3] == 0u) + (w[5] == 0u) + (w[7] == 0u) + (w[9] == 0u);
    g_is64 = (z == 5) ? 1 : 0;
}

__device__ __forceinline__ void load_edge(const void* ei, int e, int E, int& s, int& d) {
    if (g_is64) {
        const long long* p = (const long long*)ei;
        s = (int)__ldg(p + e);
        d = (int)__ldg(p + e + E);
    } else {
        const int* p = (const int*)ei;
        s = __ldg(p + e);
        d = __ldg(p + e + E);
    }
}

// ---------------------------------------------------------------------------
// init: h0 = normalize(x) -> out[0]; zero histogram. One warp per row.
// ---------------------------------------------------------------------------
__global__ __launch_bounds__(256) void init_kernel(
    const float* __restrict__ x, float* __restrict__ out0)
{
    int gt   = blockIdx.x * blockDim.x + threadIdx.x;
    if (gt < NNODES) g_cnt[gt] = 0;
    int row  = gt >> 5;
    int lane = threadIdx.x & 31;
    if (row >= NNODES) return;
    float4 v = __ldg((const float4*)(x + (size_t)row * DIM) + lane);
    float ss = v.x*v.x + v.y*v.y + v.z*v.z + v.w*v.w;
#pragma unroll
    for (int o = 16; o; o >>= 1) ss += __shfl_xor_sync(0xffffffffu, ss, o);
    float inv = 1.0f / fmaxf(sqrtf(ss), 1e-12f);
    v.x *= inv; v.y *= inv; v.z *= inv; v.w *= inv;
    ((float4*)(out0 + (size_t)row * DIM))[lane] = v;
}

// ---------------------------------------------------------------------------
// counting sort by dst: histogram -> 3-pass scan -> scatter
// ---------------------------------------------------------------------------
__global__ __launch_bounds__(256) void hist_kernel(const void* __restrict__ ei, int E) {
    for (int e = blockIdx.x * blockDim.x + threadIdx.x; e < E; e += gridDim.x * blockDim.x) {
        int s, d; load_edge(ei, e, E, s, d);
        atomicAdd(&g_cnt[d], 1);
    }
}

__global__ __launch_bounds__(256) void scan1_kernel() {
    __shared__ int sm[8];
    int t = threadIdx.x;
    int i = blockIdx.x * 256 + t;
    int v = (i < NNODES) ? g_cnt[i] : 0;
#pragma unroll
    for (int o = 16; o; o >>= 1) v += __shfl_xor_sync(0xffffffffu, v, o);
    if ((t & 31) == 0) sm[t >> 5] = v;
    __syncthreads();
    if (t == 0) {
        int s = 0;
#pragma unroll
        for (int w = 0; w < 8; ++w) s += sm[w];
        g_part[blockIdx.x] = s;
    }
}

__global__ __launch_bounds__(256) void scan2_kernel() {
    __shared__ int sm[256];
    int t = threadIdx.x;
    sm[t] = (t < NCHUNK) ? g_part[t] : 0;
    __syncthreads();
#pragma unroll
    for (int o = 1; o < 256; o <<= 1) {
        int add = (t >= o) ? sm[t - o] : 0;
        __syncthreads();
        sm[t] += add;
        __syncthreads();
    }
    if (t < NCHUNK) g_part[t] = (t == 0) ? 0 : sm[t - 1];   // exclusive
}

__global__ __launch_bounds__(256) void scan3_kernel(int E) {
    __shared__ int sm[256];
    int t = threadIdx.x;
    int i = blockIdx.x * 256 + t;
    int v = (i < NNODES) ? g_cnt[i] : 0;
    sm[t] = v;
    __syncthreads();
#pragma unroll
    for (int o = 1; o < 256; o <<= 1) {
        int add = (t >= o) ? sm[t - o] : 0;
        __syncthreads();
        sm[t] += add;
        __syncthreads();
    }
    int excl = (t == 0) ? 0 : sm[t - 1];
    int off = g_part[blockIdx.x] + excl;
    if (i < NNODES) { g_off[i] = off; g_cur[i] = off; }
    if (blockIdx.x == 0 && t == 0) g_off[NNODES] = E;
}

__global__ __launch_bounds__(256) void scatter_kernel(const void* __restrict__ ei, int E) {
    for (int e = blockIdx.x * blockDim.x + threadIdx.x; e < E; e += gridDim.x * blockDim.x) {
        int s, d; load_edge(ei, e, E, s, d);
        int pos = atomicAdd(&g_cur[d], 1);
        g_src[pos] = s;
    }
}

// ---------------------------------------------------------------------------
// fused hop: one warp per dst node. Register segment-sum over its sorted
// in-edges (no atomics, h[dst] read once), then noise + normalize + store.
// ---------------------------------------------------------------------------
__global__ __launch_bounds__(256) void hop_fused_kernel(
    const float* __restrict__ h, float* __restrict__ out,
    unsigned k0, unsigned k1)
{
    int row  = (blockIdx.x * blockDim.x + threadIdx.x) >> 5;
    int lane = threadIdx.x & 31;
    if (row >= NNODES) return;

    int start = g_off[row];
    int end   = g_off[row + 1];

    float4 b = __ldg((const float4*)(h + (size_t)row * DIM) + lane);
    float4 acc = make_float4(0.f, 0.f, 0.f, 0.f);

    for (int j0 = start; j0 < end; j0 += 32) {
        int n = min(32, end - j0);
        int idx = (lane < n) ? __ldg(g_src + j0 + lane) : 0;

        // 1-deep software pipeline on the gather
        int s0 = __shfl_sync(0xffffffffu, idx, 0);
        float4 a = __ldg((const float4*)(h + (size_t)s0 * DIM) + lane);
        for (int t = 0; t < n; ++t) {
            float4 cur = a;
            if (t + 1 < n) {
                int sn = __shfl_sync(0xffffffffu, idx, t + 1);
                a = __ldg((const float4*)(h + (size_t)sn * DIM) + lane);
            }
            float dot = cur.x*b.x + cur.y*b.y + cur.z*b.z + cur.w*b.w;
#pragma unroll
            for (int o = 16; o; o >>= 1) dot += __shfl_xor_sync(0xffffffffu, dot, o);
            float alpha = __fdividef(1.0f, 1.0f + __expf(-dot));
            acc.x = fmaf(alpha, cur.x, acc.x);
            acc.y = fmaf(alpha, cur.y, acc.y);
            acc.z = fmaf(alpha, cur.z, acc.z);
            acc.w = fmaf(alpha, cur.w, acc.w);
        }
    }

    unsigned base = (unsigned)row * DIM + (unsigned)lane * 4;
    acc.x += SIGMA_F * jax_normal(k0, k1, base + 0);
    acc.y += SIGMA_F * jax_normal(k0, k1, base + 1);
    acc.z += SIGMA_F * jax_normal(k0, k1, base + 2);
    acc.w += SIGMA_F * jax_normal(k0, k1, base + 3);

    float ss = acc.x*acc.x + acc.y*acc.y + acc.z*acc.z + acc.w*acc.w;
#pragma unroll
    for (int o = 16; o; o >>= 1) ss += __shfl_xor_sync(0xffffffffu, ss, o);
    float inv = 1.0f / fmaxf(sqrtf(ss), 1e-12f);
    acc.x *= inv; acc.y *= inv; acc.z *= inv; acc.w *= inv;

    ((float4*)(out + (size_t)row * DIM))[lane] = acc;
}

// ---------------------------------------------------------------------------
// launch
// ---------------------------------------------------------------------------
extern "C" void kernel_launch(void* const* d_in, const int* in_sizes, int n_in,
                              void* d_out, int out_size)
{
    int i_x = 0, i_e = 1;
    if (in_sizes[0] != NNODES * DIM) { i_x = 1; i_e = 0; }
    const float* x  = (const float*)d_in[i_x];
    const void*  ei = d_in[i_e];
    int E = in_sizes[i_e] / 2;

    float* out = (float*)d_out;

    // fold-like split of jax.random.key(1) into NHOPS subkeys (exact)
    unsigned keys[NHOPS][2];
    for (unsigned k = 0; k < NHOPS; ++k)
        threefry2x32(0u, 1u, 0u, k, keys[k][0], keys[k][1]);

    const int ROW_BLOCKS  = (NNODES * 32 + 255) / 256;
    const int EDGE_BLOCKS = (E + 255) / 256;

    detect_kernel<<<1, 1>>>((const unsigned*)ei);
    init_kernel<<<ROW_BLOCKS, 256>>>(x, out);
    hist_kernel<<<EDGE_BLOCKS, 256>>>(ei, E);
    scan1_kernel<<<NCHUNK, 256>>>();
    scan2_kernel<<<1, 256>>>();
    scan3_kernel<<<NCHUNK, 256>>>(E);
    scatter_kernel<<<EDGE_BLOCKS, 256>>>(ei, E);

    for (int k = 0; k < NHOPS; ++k) {
        hop_fused_kernel<<<ROW_BLOCKS, 256>>>(out + (size_t)k * NNODES * DIM,
                                              out + (size_t)(k + 1) * NNODES * DIM,
                                              keys[k][0], keys[k][1]);
    }
}